// round 6
// baseline (speedup 1.0000x reference)
#include <cuda_runtime.h>
#include <math.h>

#define NB 8
#define NN 300
#define NR 36
#define NC 256
#define NWRD 10   // ceil(300/32)

// Scratch: per (batch, roi-slot): x1,y1,x2,y2, level(int bits), valid(int bits)
__device__ float g_roi[NB * NR * 6];

// ---------------------------------------------------------------------------
// Kernel A: per-batch NMS + selection + level assignment
// ---------------------------------------------------------------------------
__global__ __launch_bounds__(256) void nms_kernel(const float* __restrict__ boxes,
                                                  const float* __restrict__ scores)
{
    __shared__ float    s_s[NN];
    __shared__ float    s_bx[NN * 4];
    __shared__ float    s_area[NN];
    __shared__ int      s_order[NN];
    __shared__ unsigned s_mask[NN][NWRD];
    __shared__ unsigned s_vbits[NWRD];
    __shared__ unsigned s_keepbits[NWRD];
    __shared__ int      s_sel[NR];
    __shared__ int      s_selv[NR];

    const int b = blockIdx.x;
    const int t = threadIdx.x;
    const float* bx = boxes + (size_t)b * NN * 4;
    const float* sc = scores + (size_t)b * NN;

    if (t < NWRD) s_vbits[t] = 0u;

    // s = scores if > CONF_THR else -inf
    for (int i = t; i < NN; i += 256) {
        float v = sc[i];
        s_s[i] = (v > 0.3f) ? v : -INFINITY;
    }
    __syncthreads();

    // stable descending rank (exactly matches jnp.argsort(-s), stable).
    // Ties (including the -inf group: -inf == -inf) break by ascending index.
    for (int i = t; i < NN; i += 256) {
        float si = s_s[i];
        int r = 0;
        for (int j = 0; j < NN; j++) {
            float sj = s_s[j];
            r += (int)((sj > si) || (sj == si && j < i));
        }
        s_order[r] = i;
    }
    __syncthreads();

    // gather sorted boxes, areas, valid bits
    for (int k = t; k < NN; k += 256) {
        int i = s_order[k];
        float x1 = bx[i*4+0], y1 = bx[i*4+1], x2 = bx[i*4+2], y2 = bx[i*4+3];
        s_bx[k*4+0] = x1; s_bx[k*4+1] = y1; s_bx[k*4+2] = x2; s_bx[k*4+3] = y2;
        s_area[k] = (x2 - x1) * (y2 - y1);
        if (s_s[i] > -INFINITY) atomicOr(&s_vbits[k >> 5], 1u << (k & 31));
    }
    __syncthreads();

    // suppression bitmask: bit (i,j) set iff j>i and iou(i,j) > 0.7
    for (int task = t; task < NN * NWRD; task += 256) {
        int i = task / NWRD;
        int w = task - i * NWRD;
        float ax1 = s_bx[i*4+0], ay1 = s_bx[i*4+1];
        float ax2 = s_bx[i*4+2], ay2 = s_bx[i*4+3];
        float aarea = s_area[i];
        unsigned m = 0;
        int jend = min(NN, (w + 1) * 32);
        for (int j = max(w * 32, i + 1); j < jend; j++) {
            float ltx = fmaxf(ax1, s_bx[j*4+0]);
            float lty = fmaxf(ay1, s_bx[j*4+1]);
            float rbx = fminf(ax2, s_bx[j*4+2]);
            float rby = fminf(ay2, s_bx[j*4+3]);
            float iw = fmaxf(rbx - ltx, 0.f);
            float ih = fmaxf(rby - lty, 0.f);
            float inter = iw * ih;
            float iou = inter / (aarea + s_area[j] - inter + 1e-9f);
            if (iou > 0.7f) m |= 1u << (j & 31);
        }
        s_mask[i][w] = m;
    }
    __syncthreads();

    // serial greedy scan (exact fori_loop semantics) + stable 0/1 selection
    if (t == 0) {
        unsigned removed[NWRD];
        #pragma unroll
        for (int w = 0; w < NWRD; w++) removed[w] = 0u;
        for (int i = 0; i < NN; i++) {
            unsigned bit = 1u << (i & 31);
            if ((s_vbits[i >> 5] & bit) && !(removed[i >> 5] & bit)) {
                #pragma unroll
                for (int w = 0; w < NWRD; w++) removed[w] |= s_mask[i][w];
            }
        }
        #pragma unroll
        for (int w = 0; w < NWRD; w++) s_keepbits[w] = s_vbits[w] & ~removed[w];

        int cnt = 0;
        for (int i = 0; i < NN && cnt < NR; i++)
            if (s_keepbits[i >> 5] & (1u << (i & 31))) { s_sel[cnt] = i; s_selv[cnt] = 1; cnt++; }
        for (int i = 0; i < NN && cnt < NR; i++)
            if (!(s_keepbits[i >> 5] & (1u << (i & 31)))) { s_sel[cnt] = i; s_selv[cnt] = 0; cnt++; }
    }
    __syncthreads();

    if (t < NR) {
        int k = s_sel[t];
        float x1 = s_bx[k*4+0], y1 = s_bx[k*4+1], x2 = s_bx[k*4+2], y2 = s_bx[k*4+3];
        float dx = x2 - x1, dy = y2 - y1;
        float size = sqrtf(fmaxf(dx*dx + dy*dy, 1e-12f));
        float lf = floorf(4.0f + log2f(size / 224.0f * 4.0f));
        lf = fminf(fmaxf(lf, 2.0f), 5.0f);
        int level = (int)lf - 2;
        float* o = g_roi + (size_t)(b * NR + t) * 6;
        o[0] = x1; o[1] = y1; o[2] = x2; o[3] = y2;
        o[4] = __int_as_float(level);
        o[5] = __int_as_float(s_selv[t]);
    }
}

// ---------------------------------------------------------------------------
// Kernel B: bilinear ROI pooling, block = (roi, batch), thread = channel
// ---------------------------------------------------------------------------
__global__ __launch_bounds__(NC) void pool_kernel(const float* __restrict__ f0,
                                                  const float* __restrict__ f1,
                                                  const float* __restrict__ f2,
                                                  const float* __restrict__ f3,
                                                  float* __restrict__ out)
{
    const int r = blockIdx.x;
    const int b = blockIdx.y;
    const int c = threadIdx.x;

    const float* info = g_roi + (size_t)(b * NR + r) * 6;
    float* o = out + ((size_t)(b * NR + r)) * NC + c;

    int valid = __float_as_int(info[5]);
    if (!valid) { *o = 0.f; return; }   // uniform branch within block

    int level = __float_as_int(info[4]) & 3;  // defensive: 0..3
    int H = 200 >> level;                     // 200,100,50,25
    int W = H;
    const float* fl = (level == 0) ? f0 : (level == 1) ? f1 : (level == 2) ? f2 : f3;

    __shared__ int   sy0[14], sy1[14], sx0[14], sx1[14];
    __shared__ float sly[14], slx[14];
    __shared__ int   sob[28];           // [0..13]=y oob, [14..27]=x oob

    if (c < 28) {
        int isx = (c >= 14);
        int k = c - (isx ? 14 : 0);
        float lo  = isx ? info[0] : info[1];
        float hi  = isx ? info[2] : info[3];
        float ext = fmaxf(hi - lo, 1.0f);
        float g = ((float)k + 0.5f) / 14.0f;
        float P = lo + ext * g;             // unclipped coord -> oob test
        int lim = isx ? W : H;
        int ob = (P < -1.0f) || (P > (float)lim);
        float p = fminf(fmaxf(P, 0.0f), (float)(lim - 1));
        int p0 = (int)floorf(p);
        p0 = min(max(p0, 0), lim - 1);      // defensive clamp (no OOB possible)
        int p1 = min(p0 + 1, lim - 1);
        float lp = p - (float)p0;
        if (isx) { sx0[k] = p0; sx1[k] = p1; slx[k] = lp; }
        else     { sy0[k] = p0; sy1[k] = p1; sly[k] = lp; }
        sob[c] = ob;
    }
    __syncthreads();

    const float* plane = fl + (size_t)(b * NC + c) * (size_t)(H * W);

    float sum = 0.f;
    for (int iy = 0; iy < 14; iy++) {
        if (sob[iy]) continue;
        const float* ra = plane + sy0[iy] * W;
        const float* rb = plane + sy1[iy] * W;
        float ly = sly[iy];
        float wy = 1.f - ly;
        #pragma unroll
        for (int ix = 0; ix < 14; ix++) {
            if (sob[14 + ix]) continue;
            int x0 = sx0[ix], x1 = sx1[ix];
            float lx = slx[ix];
            float f00 = __ldg(ra + x0);
            float f01 = __ldg(ra + x1);
            float f10 = __ldg(rb + x0);
            float f11 = __ldg(rb + x1);
            float top = f00 * wy + f10 * ly;
            float bot = f01 * wy + f11 * ly;
            sum += top * (1.f - lx) + bot * lx;
        }
    }
    *o = sum / 196.0f;   // mean over full 14x14 grid (oob samples contribute 0)
}

// ---------------------------------------------------------------------------
extern "C" void kernel_launch(void* const* d_in, const int* in_sizes, int n_in,
                              void* d_out, int out_size)
{
    // Identify inputs by element count (all six are distinct sizes):
    //   boxes  = 8*300*4      = 9600
    //   scores = 8*300        = 2400
    //   feat0  = 8*256*200^2  = 81,920,000
    //   feat1  = 8*256*100^2  = 20,480,000
    //   feat2  = 8*256*50^2   =  5,120,000
    //   feat3  = 8*256*25^2   =  1,280,000
    const float* boxes  = nullptr;
    const float* scores = nullptr;
    const float* f0 = nullptr;
    const float* f1 = nullptr;
    const float* f2 = nullptr;
    const float* f3 = nullptr;
    for (int i = 0; i < n_in; i++) {
        switch (in_sizes[i]) {
            case 9600:     boxes  = (const float*)d_in[i]; break;
            case 2400:     scores = (const float*)d_in[i]; break;
            case 81920000: f0     = (const float*)d_in[i]; break;
            case 20480000: f1     = (const float*)d_in[i]; break;
            case 5120000:  f2     = (const float*)d_in[i]; break;
            case 1280000:  f3     = (const float*)d_in[i]; break;
            default: break;
        }
    }
    // Fallback to positional order if size-matching failed for any input.
    if (!boxes || !scores || !f0 || !f1 || !f2 || !f3) {
        boxes  = (const float*)d_in[0];
        scores = (const float*)d_in[1];
        f0     = (const float*)d_in[2];
        f1     = (const float*)d_in[3];
        f2     = (const float*)d_in[4];
        f3     = (const float*)d_in[5];
    }
    float* out = (float*)d_out;

    nms_kernel<<<NB, 256>>>(boxes, scores);
    dim3 g(NR, NB);
    pool_kernel<<<g, NC>>>(f0, f1, f2, f3, out);
}